// round 4
// baseline (speedup 1.0000x reference)
#include <cuda_runtime.h>
#include <math.h>
#include <stdint.h>

// Problem constants
#define T_STEPS  256
#define BATCH    64
#define VOCAB    32000
#define D_EMBED  512
#define D_HIDDEN 1024
#define G4       (4 * D_HIDDEN)          // 4096
#define NH       (BATCH * D_HIDDEN)      // 65536

// Scratch
__device__ float    g_xgates[(size_t)T_STEPS * BATCH * G4];   // 256 MiB fp32
__device__ float    g_cstate[NH];                             // cell state
__device__ unsigned g_emb_tf32[(size_t)VOCAB * D_EMBED];      // tf32 bits
__device__ unsigned g_wih_tf32[(size_t)G4 * D_EMBED];
__device__ unsigned g_whh_tf32[(size_t)G4 * D_HIDDEN];
__device__ unsigned g_h_tf32[2][NH];                          // ping-pong h (tf32)

// ---------------------------------------------------------------------------
// Helpers
// ---------------------------------------------------------------------------
__device__ __forceinline__ unsigned f2tf32(float f) {
    unsigned u;
    asm("cvt.rna.tf32.f32 %0, %1;" : "=r"(u) : "f"(f));
    return u;
}

__device__ __forceinline__ void cpa16(unsigned dst_s, const void* src) {
    asm volatile("cp.async.cg.shared.global [%0], [%1], 16;" :: "r"(dst_s), "l"(src));
}
__device__ __forceinline__ void cpa_commit() {
    asm volatile("cp.async.commit_group;");
}
__device__ __forceinline__ void cpa_wait1() {
    asm volatile("cp.async.wait_group 1;");
}
__device__ __forceinline__ void cpa_wait0() {
    asm volatile("cp.async.wait_group 0;");
}

__device__ __forceinline__ void mma_tf32(float c[4],
                                         unsigned a0, unsigned a1, unsigned a2, unsigned a3,
                                         unsigned b0, unsigned b1) {
    asm volatile(
        "mma.sync.aligned.m16n8k8.row.col.f32.tf32.tf32.f32 "
        "{%0,%1,%2,%3}, {%4,%5,%6,%7}, {%8,%9}, {%0,%1,%2,%3};"
        : "+f"(c[0]), "+f"(c[1]), "+f"(c[2]), "+f"(c[3])
        : "r"(a0), "r"(a1), "r"(a2), "r"(a3), "r"(b0), "r"(b1));
}

// ---------------------------------------------------------------------------
// Init: zero cell state (fresh every launch for graph replay)
// ---------------------------------------------------------------------------
__global__ void init_kernel() {
    int i = blockIdx.x * blockDim.x + threadIdx.x;
    if (i < NH) g_cstate[i] = 0.0f;
}

// ---------------------------------------------------------------------------
// fp32 -> tf32 (rna) bulk convert, vectorized x4
// ---------------------------------------------------------------------------
__global__ void cvt_tf32_kernel(const float4* __restrict__ src,
                                uint4* __restrict__ dst, int n4) {
    int i = blockIdx.x * blockDim.x + threadIdx.x;
    if (i < n4) {
        float4 v = src[i];
        uint4 o;
        o.x = f2tf32(v.x); o.y = f2tf32(v.y);
        o.z = f2tf32(v.z); o.w = f2tf32(v.w);
        dst[i] = o;
    }
}

// ---------------------------------------------------------------------------
// Embed gather + input GEMM (tf32 tensor cores):
//   x_gates[m][n] = sum_k emb[x_seq[m]][k] * W_ih[n][k] + b_ih[n] + b_hh[n]
// M=16384, N=4096, K=512.  CTA tile 128x128, BK=32, 256 threads (8 warps),
// warp tile 32x64 (2 x 8 atoms of m16n8k8). 2-stage cp.async pipeline.
// Dynamic smem: a[2][128][36], b[2][128][36], tok[128].
// ---------------------------------------------------------------------------
#define EA_STRIDE 36
#define EA_BUF    (128 * EA_STRIDE)      // 4608
#define E_B_OFF   (2 * EA_BUF)           // 9216
#define E_TOK_OFF (4 * EA_BUF)           // 18432
#define E_SMEM_WORDS (E_TOK_OFF + 128)   // 18560
#define E_SMEM_BYTES (E_SMEM_WORDS * 4)  // 74240

__global__ __launch_bounds__(256, 1)
void embed_gemm_tf32(const int* __restrict__ x_seq,
                     const float* __restrict__ b_ih,
                     const float* __restrict__ b_hh) {
    extern __shared__ unsigned smem[];
    unsigned* a_s = smem;
    unsigned* b_s = smem + E_B_OFF;
    int*      tok = (int*)(smem + E_TOK_OFF);

    const int tid  = threadIdx.x;
    const int nblk = blockIdx.x * 128;
    const int mblk = blockIdx.y * 128;

    if (tid < 128) tok[tid] = x_seq[mblk + tid];
    __syncthreads();

    const int w    = tid >> 5;
    const int lane = tid & 31;
    const int g    = lane >> 2;
    const int tig  = lane & 3;
    const int m0   = (w & 3) * 32;
    const int n0   = (w >> 2) * 64;

    // loader indices: 128 rows x 32 cols, 16 floats/thread
    const int lrow = tid >> 1;
    const int lc0  = (tid & 1) * 16;

    const unsigned sbase = (unsigned)__cvta_generic_to_shared(smem);

    float cfr[2][8][4];
#pragma unroll
    for (int mi = 0; mi < 2; mi++)
#pragma unroll
        for (int ni = 0; ni < 8; ni++)
#pragma unroll
            for (int q = 0; q < 4; q++) cfr[mi][ni][q] = 0.0f;

    const unsigned* asrc_row = g_emb_tf32 + (size_t)tok[lrow] * D_EMBED + lc0;
    const unsigned* bsrc_row = g_wih_tf32 + (size_t)(nblk + lrow) * D_EMBED + lc0;

    auto load_chunk = [&](int kc, int buf) {
        unsigned adst = sbase + (buf * EA_BUF + lrow * EA_STRIDE + lc0) * 4;
        const unsigned* asrc = asrc_row + kc * 32;
#pragma unroll
        for (int s = 0; s < 4; s++) cpa16(adst + s * 16, asrc + s * 4);
        unsigned bdst = sbase + (E_B_OFF + buf * EA_BUF + lrow * EA_STRIDE + lc0) * 4;
        const unsigned* bsrc = bsrc_row + kc * 32;
#pragma unroll
        for (int s = 0; s < 4; s++) cpa16(bdst + s * 16, bsrc + s * 4);
    };

    load_chunk(0, 0);
    cpa_commit();

    for (int kc = 0; kc < 16; kc++) {       // K = 512 / 32
        const int buf = kc & 1;
        if (kc + 1 < 16) {
            load_chunk(kc + 1, buf ^ 1);
            cpa_commit();
            cpa_wait1();
        } else {
            cpa_wait0();
        }
        __syncthreads();

        const unsigned* A = a_s + buf * EA_BUF;
        const unsigned* B = b_s + buf * EA_BUF;
#pragma unroll
        for (int k8 = 0; k8 < 32; k8 += 8) {
            unsigned afr[2][4];
#pragma unroll
            for (int mi = 0; mi < 2; mi++) {
                const int r = m0 + mi * 16 + g;
                afr[mi][0] = A[r * EA_STRIDE + k8 + tig];
                afr[mi][1] = A[(r + 8) * EA_STRIDE + k8 + tig];
                afr[mi][2] = A[r * EA_STRIDE + k8 + tig + 4];
                afr[mi][3] = A[(r + 8) * EA_STRIDE + k8 + tig + 4];
            }
#pragma unroll
            for (int ni = 0; ni < 8; ni++) {
                const int r = n0 + ni * 8 + g;
                unsigned b0 = B[r * EA_STRIDE + k8 + tig];
                unsigned b1 = B[r * EA_STRIDE + k8 + tig + 4];
#pragma unroll
                for (int mi = 0; mi < 2; mi++)
                    mma_tf32(cfr[mi][ni], afr[mi][0], afr[mi][1], afr[mi][2], afr[mi][3], b0, b1);
            }
        }
        __syncthreads();
    }

    // Epilogue: add bias, write fp32 x_gates
#pragma unroll
    for (int ni = 0; ni < 8; ni++) {
        const int col = nblk + n0 + ni * 8 + 2 * tig;
        const float bi0 = b_ih[col] + b_hh[col];
        const float bi1 = b_ih[col + 1] + b_hh[col + 1];
#pragma unroll
        for (int mi = 0; mi < 2; mi++) {
            const int row = mblk + m0 + mi * 16 + g;
            float2 v0 = make_float2(cfr[mi][ni][0] + bi0, cfr[mi][ni][1] + bi1);
            float2 v1 = make_float2(cfr[mi][ni][2] + bi0, cfr[mi][ni][3] + bi1);
            *(float2*)&g_xgates[(size_t)row * G4 + col] = v0;
            *(float2*)&g_xgates[(size_t)(row + 8) * G4 + col] = v1;
        }
    }
}

// ---------------------------------------------------------------------------
// One LSTM step (tf32 tensor cores), fused with activations + cell update.
// Grid 128 CTAs x 256 threads. CTA owns 8 hidden units j0..j0+7 => 32 gate
// rows arranged locally as nl = gate*8 + u  (W_hh row = gate*1024 + j0 + u).
// gates[64 x 32] = h_prev[64 x 1024] * Wtile^T, K pipelined in BK=64 chunks.
// 8 warps, warp tile m16 x n16 (2 atoms).
// Dynamic smem: a[2][64][68], b[2][32][68], gs[64][33].
// ---------------------------------------------------------------------------
#define SA_STRIDE 68
#define SA_BUF    (64 * SA_STRIDE)       // 4352
#define S_B_OFF   (2 * SA_BUF)           // 8704
#define SB_BUF    (32 * SA_STRIDE)       // 2176
#define S_GS_OFF  (S_B_OFF + 2 * SB_BUF) // 13056
#define S_SMEM_WORDS (S_GS_OFF + 64 * 33) // 15168
#define S_SMEM_BYTES (S_SMEM_WORDS * 4)   // 60672

__global__ __launch_bounds__(256, 1)
void lstm_step_tf32(int t, float* __restrict__ outs) {
    extern __shared__ unsigned smem[];
    unsigned* a_s = smem;
    unsigned* b_s = smem + S_B_OFF;
    float*    gs  = (float*)(smem + S_GS_OFF);

    const int tid  = threadIdx.x;
    const int j0   = blockIdx.x * 8;
    const int w    = tid >> 5;
    const int lane = tid & 31;
    const int g    = lane >> 2;
    const int tig  = lane & 3;
    const int m0   = (w & 3) * 16;       // batch base
    const int n0   = (w >> 2) * 16;      // local gate-row base

    float cfr[2][4];
#pragma unroll
    for (int na = 0; na < 2; na++)
#pragma unroll
        for (int q = 0; q < 4; q++) cfr[na][q] = 0.0f;

    if (t > 0) {
        const unsigned sbase = (unsigned)__cvta_generic_to_shared(smem);
        const unsigned* hsrc = g_h_tf32[(t - 1) & 1];

        const int arow = tid >> 2;             // 0..63
        const int ac0  = (tid & 3) * 16;       // 16 floats
        const int brow = tid >> 3;             // 0..31
        const int bc0  = (tid & 7) * 8;        // 8 floats
        const int wrow = (brow >> 3) * D_HIDDEN + j0 + (brow & 7);

        const unsigned* asrc_row = hsrc + (size_t)arow * D_HIDDEN + ac0;
        const unsigned* bsrc_row = g_whh_tf32 + (size_t)wrow * D_HIDDEN + bc0;

        auto load_chunk = [&](int kc, int buf) {
            unsigned adst = sbase + (buf * SA_BUF + arow * SA_STRIDE + ac0) * 4;
            const unsigned* asrc = asrc_row + kc * 64;
#pragma unroll
            for (int s = 0; s < 4; s++) cpa16(adst + s * 16, asrc + s * 4);
            unsigned bdst = sbase + (S_B_OFF + buf * SB_BUF + brow * SA_STRIDE + bc0) * 4;
            const unsigned* bsrc = bsrc_row + kc * 64;
            cpa16(bdst, bsrc);
            cpa16(bdst + 16, bsrc + 4);
        };

        load_chunk(0, 0);
        cpa_commit();

        for (int kc = 0; kc < 16; kc++) {     // K = 1024 / 64
            const int buf = kc & 1;
            if (kc + 1 < 16) {
                load_chunk(kc + 1, buf ^ 1);
                cpa_commit();
                cpa_wait1();
            } else {
                cpa_wait0();
            }
            __syncthreads();

            const unsigned* A = a_s + buf * SA_BUF;
            const unsigned* B = b_s + buf * SB_BUF;
#pragma unroll
            for (int k8 = 0; k8 < 64; k8 += 8) {
                unsigned a0 = A[(m0 + g) * SA_STRIDE + k8 + tig];
                unsigned a1 = A[(m0 + g + 8) * SA_STRIDE + k8 + tig];
                unsigned a2 = A[(m0 + g) * SA_STRIDE + k8 + tig + 4];
                unsigned a3 = A[(m0 + g + 8) * SA_STRIDE + k8 + tig + 4];
#pragma unroll
                for (int na = 0; na < 2; na++) {
                    const int r = n0 + na * 8 + g;
                    unsigned b0 = B[r * SA_STRIDE + k8 + tig];
                    unsigned b1 = B[r * SA_STRIDE + k8 + tig + 4];
                    mma_tf32(cfr[na], a0, a1, a2, a3, b0, b1);
                }
            }
            __syncthreads();
        }
    }

    // Stage gate accumulators to smem (zeros when t==0)
#pragma unroll
    for (int na = 0; na < 2; na++) {
        const int c = n0 + na * 8 + 2 * tig;
        gs[(m0 + g) * 33 + c]         = cfr[na][0];
        gs[(m0 + g) * 33 + c + 1]     = cfr[na][1];
        gs[(m0 + g + 8) * 33 + c]     = cfr[na][2];
        gs[(m0 + g + 8) * 33 + c + 1] = cfr[na][3];
    }
    __syncthreads();

    // Fused elementwise: 256 threads x 2 cells = 64 batches x 8 units
    const float* xg   = g_xgates + (size_t)t * BATCH * G4;
    float*       hout = outs + (size_t)t * NH;
    unsigned*    htf  = g_h_tf32[t & 1];
#pragma unroll
    for (int ci = 0; ci < 2; ci++) {
        const int cell = tid * 2 + ci;       // 0..511
        const int b = cell >> 3;
        const int u = cell & 7;
        const int j = j0 + u;
        const size_t xrow = (size_t)b * G4;
        const float gi = gs[b * 33 + u]      + xg[xrow + j];
        const float gf = gs[b * 33 + 8 + u]  + xg[xrow + D_HIDDEN + j];
        const float gg = gs[b * 33 + 16 + u] + xg[xrow + 2 * D_HIDDEN + j];
        const float go = gs[b * 33 + 24 + u] + xg[xrow + 3 * D_HIDDEN + j];
        const float si = 1.0f / (1.0f + expf(-gi));
        const float sf = 1.0f / (1.0f + expf(-gf));
        const float tg = tanhf(gg);
        const float so = 1.0f / (1.0f + expf(-go));
        const float cp = g_cstate[b * D_HIDDEN + j];
        const float cn = sf * cp + si * tg;
        g_cstate[b * D_HIDDEN + j] = cn;
        const float hn = so * tanhf(cn);
        hout[(size_t)b * D_HIDDEN + j] = hn;
        htf[b * D_HIDDEN + j] = f2tf32(hn);
    }
}

// ---------------------------------------------------------------------------
// Append final h (= outs[T-1]) and c, if the output expects them.
// ---------------------------------------------------------------------------
__global__ void finalize_kernel(float* __restrict__ out, int out_size) {
    int i = blockIdx.x * blockDim.x + threadIdx.x;
    const size_t base = (size_t)T_STEPS * NH;
    if ((size_t)out_size >= base + 2 * (size_t)NH && i < NH) {
        out[base + i]      = out[(size_t)(T_STEPS - 1) * NH + i];
        out[base + NH + i] = g_cstate[i];
    }
}

// ---------------------------------------------------------------------------
extern "C" void kernel_launch(void* const* d_in, const int* in_sizes, int n_in,
                              void* d_out, int out_size)
{
    const int*   x_seq = (const int*)  d_in[0];
    const float* emb   = (const float*)d_in[1];
    const float* W_ih  = (const float*)d_in[2];
    const float* W_hh  = (const float*)d_in[3];
    const float* b_ih  = (const float*)d_in[4];
    const float* b_hh  = (const float*)d_in[5];
    float* out = (float*)d_out;

    static bool attr_done = false;
    if (!attr_done) {
        cudaFuncSetAttribute(embed_gemm_tf32,
                             cudaFuncAttributeMaxDynamicSharedMemorySize, E_SMEM_BYTES);
        cudaFuncSetAttribute(lstm_step_tf32,
                             cudaFuncAttributeMaxDynamicSharedMemorySize, S_SMEM_BYTES);
        attr_done = true;
    }

    init_kernel<<<(NH + 255) / 256, 256>>>();

    // Pre-convert weights/embedding to tf32 (rna) scratch
    {
        unsigned* demb; cudaGetSymbolAddress((void**)&demb, g_emb_tf32);
        unsigned* dwih; cudaGetSymbolAddress((void**)&dwih, g_wih_tf32);
        unsigned* dwhh; cudaGetSymbolAddress((void**)&dwhh, g_whh_tf32);
        int n4e = (VOCAB * D_EMBED) / 4;
        int n4i = (G4 * D_EMBED) / 4;
        int n4h = (G4 * D_HIDDEN) / 4;
        cvt_tf32_kernel<<<(n4e + 255) / 256, 256>>>((const float4*)emb,  (uint4*)demb, n4e);
        cvt_tf32_kernel<<<(n4i + 255) / 256, 256>>>((const float4*)W_ih, (uint4*)dwih, n4i);
        cvt_tf32_kernel<<<(n4h + 255) / 256, 256>>>((const float4*)W_hh, (uint4*)dwhh, n4h);
    }

    dim3 eg(G4 / 128, (T_STEPS * BATCH) / 128);   // (32, 128)
    embed_gemm_tf32<<<eg, 256, E_SMEM_BYTES>>>(x_seq, b_ih, b_hh);

    for (int t = 0; t < T_STEPS; t++)
        lstm_step_tf32<<<128, 256, S_SMEM_BYTES>>>(t, out);

    finalize_kernel<<<(NH + 255) / 256, 256>>>(out, out_size);
}

// round 5
// speedup vs baseline: 1.0629x; 1.0629x over previous
#include <cuda_runtime.h>
#include <math.h>
#include <stdint.h>

// Problem constants
#define T_STEPS  256
#define BATCH    64
#define VOCAB    32000
#define D_EMBED  512
#define D_HIDDEN 1024
#define G4       (4 * D_HIDDEN)          // 4096
#define NH       (BATCH * D_HIDDEN)      // 65536
#define NCTA     128

// Scratch
__device__ float    g_xgates[(size_t)T_STEPS * BATCH * G4];   // 256 MiB fp32
__device__ unsigned g_emb_tf32[(size_t)VOCAB * D_EMBED];      // tf32 bits
__device__ unsigned g_wih_tf32[(size_t)G4 * D_EMBED];
__device__ unsigned g_h_tf32[2][NH];                          // ping-pong h (tf32)
__device__ unsigned g_bar_count;
__device__ volatile unsigned g_bar_gen;

// ---------------------------------------------------------------------------
// Helpers
// ---------------------------------------------------------------------------
__device__ __forceinline__ unsigned f2tf32(float f) {
    unsigned u;
    asm("cvt.rna.tf32.f32 %0, %1;" : "=r"(u) : "f"(f));
    return u;
}

__device__ __forceinline__ void cpa16(unsigned dst_s, const void* src) {
    asm volatile("cp.async.cg.shared.global [%0], [%1], 16;" :: "r"(dst_s), "l"(src));
}
__device__ __forceinline__ void cpa_commit() {
    asm volatile("cp.async.commit_group;");
}
__device__ __forceinline__ void cpa_wait1() {
    asm volatile("cp.async.wait_group 1;");
}
__device__ __forceinline__ void cpa_wait0() {
    asm volatile("cp.async.wait_group 0;");
}

__device__ __forceinline__ void mma_tf32(float c[4],
                                         unsigned a0, unsigned a1, unsigned a2, unsigned a3,
                                         unsigned b0, unsigned b1) {
    asm volatile(
        "mma.sync.aligned.m16n8k8.row.col.f32.tf32.tf32.f32 "
        "{%0,%1,%2,%3}, {%4,%5,%6,%7}, {%8,%9}, {%0,%1,%2,%3};"
        : "+f"(c[0]), "+f"(c[1]), "+f"(c[2]), "+f"(c[3])
        : "r"(a0), "r"(a1), "r"(a2), "r"(a3), "r"(b0), "r"(b1));
}

__device__ __forceinline__ float sigf(float x) {
    return 1.0f / (1.0f + expf(-x));
}

// ---------------------------------------------------------------------------
// Init: reset grid-barrier state (fresh every launch for graph replay)
// ---------------------------------------------------------------------------
__global__ void init_kernel() {
    g_bar_count = 0;
    g_bar_gen = 0;
}

// ---------------------------------------------------------------------------
// fp32 -> tf32 (rna) bulk convert, vectorized x4
// ---------------------------------------------------------------------------
__global__ void cvt_tf32_kernel(const float4* __restrict__ src,
                                uint4* __restrict__ dst, int n4) {
    int i = blockIdx.x * blockDim.x + threadIdx.x;
    if (i < n4) {
        float4 v = src[i];
        uint4 o;
        o.x = f2tf32(v.x); o.y = f2tf32(v.y);
        o.z = f2tf32(v.z); o.w = f2tf32(v.w);
        dst[i] = o;
    }
}

// ---------------------------------------------------------------------------
// Embed gather + input GEMM (tf32 tensor cores)  [unchanged from passing R3]
//   x_gates[m][n] = sum_k emb[x_seq[m]][k] * W_ih[n][k] + b_ih[n] + b_hh[n]
// ---------------------------------------------------------------------------
#define EA_STRIDE 36
#define EA_BUF    (128 * EA_STRIDE)
#define E_B_OFF   (2 * EA_BUF)
#define E_TOK_OFF (4 * EA_BUF)
#define E_SMEM_WORDS (E_TOK_OFF + 128)
#define E_SMEM_BYTES (E_SMEM_WORDS * 4)

__global__ __launch_bounds__(256, 1)
void embed_gemm_tf32(const int* __restrict__ x_seq,
                     const float* __restrict__ b_ih,
                     const float* __restrict__ b_hh) {
    extern __shared__ unsigned smem[];
    unsigned* a_s = smem;
    unsigned* b_s = smem + E_B_OFF;
    int*      tok = (int*)(smem + E_TOK_OFF);

    const int tid  = threadIdx.x;
    const int nblk = blockIdx.x * 128;
    const int mblk = blockIdx.y * 128;

    if (tid < 128) tok[tid] = x_seq[mblk + tid];
    __syncthreads();

    const int w    = tid >> 5;
    const int lane = tid & 31;
    const int g    = lane >> 2;
    const int tig  = lane & 3;
    const int m0   = (w & 3) * 32;
    const int n0   = (w >> 2) * 64;

    const int lrow = tid >> 1;
    const int lc0  = (tid & 1) * 16;

    const unsigned sbase = (unsigned)__cvta_generic_to_shared(smem);

    float cfr[2][8][4];
#pragma unroll
    for (int mi = 0; mi < 2; mi++)
#pragma unroll
        for (int ni = 0; ni < 8; ni++)
#pragma unroll
            for (int q = 0; q < 4; q++) cfr[mi][ni][q] = 0.0f;

    const unsigned* asrc_row = g_emb_tf32 + (size_t)tok[lrow] * D_EMBED + lc0;
    const unsigned* bsrc_row = g_wih_tf32 + (size_t)(nblk + lrow) * D_EMBED + lc0;

    auto load_chunk = [&](int kc, int buf) {
        unsigned adst = sbase + (buf * EA_BUF + lrow * EA_STRIDE + lc0) * 4;
        const unsigned* asrc = asrc_row + kc * 32;
#pragma unroll
        for (int s = 0; s < 4; s++) cpa16(adst + s * 16, asrc + s * 4);
        unsigned bdst = sbase + (E_B_OFF + buf * EA_BUF + lrow * EA_STRIDE + lc0) * 4;
        const unsigned* bsrc = bsrc_row + kc * 32;
#pragma unroll
        for (int s = 0; s < 4; s++) cpa16(bdst + s * 16, bsrc + s * 4);
    };

    load_chunk(0, 0);
    cpa_commit();

    for (int kc = 0; kc < 16; kc++) {
        const int buf = kc & 1;
        if (kc + 1 < 16) {
            load_chunk(kc + 1, buf ^ 1);
            cpa_commit();
            cpa_wait1();
        } else {
            cpa_wait0();
        }
        __syncthreads();

        const unsigned* A = a_s + buf * EA_BUF;
        const unsigned* B = b_s + buf * EA_BUF;
#pragma unroll
        for (int k8 = 0; k8 < 32; k8 += 8) {
            unsigned afr[2][4];
#pragma unroll
            for (int mi = 0; mi < 2; mi++) {
                const int r = m0 + mi * 16 + g;
                afr[mi][0] = A[r * EA_STRIDE + k8 + tig];
                afr[mi][1] = A[(r + 8) * EA_STRIDE + k8 + tig];
                afr[mi][2] = A[r * EA_STRIDE + k8 + tig + 4];
                afr[mi][3] = A[(r + 8) * EA_STRIDE + k8 + tig + 4];
            }
#pragma unroll
            for (int ni = 0; ni < 8; ni++) {
                const int r = n0 + ni * 8 + g;
                unsigned b0 = B[r * EA_STRIDE + k8 + tig];
                unsigned b1 = B[r * EA_STRIDE + k8 + tig + 4];
#pragma unroll
                for (int mi = 0; mi < 2; mi++)
                    mma_tf32(cfr[mi][ni], afr[mi][0], afr[mi][1], afr[mi][2], afr[mi][3], b0, b1);
            }
        }
        __syncthreads();
    }

#pragma unroll
    for (int ni = 0; ni < 8; ni++) {
        const int col = nblk + n0 + ni * 8 + 2 * tig;
        const float bi0 = b_ih[col] + b_hh[col];
        const float bi1 = b_ih[col + 1] + b_hh[col + 1];
#pragma unroll
        for (int mi = 0; mi < 2; mi++) {
            const int row = mblk + m0 + mi * 16 + g;
            float2 v0 = make_float2(cfr[mi][ni][0] + bi0, cfr[mi][ni][1] + bi1);
            float2 v1 = make_float2(cfr[mi][ni][2] + bi0, cfr[mi][ni][3] + bi1);
            *(float2*)&g_xgates[(size_t)row * G4 + col] = v0;
            *(float2*)&g_xgates[(size_t)(row + 8) * G4 + col] = v1;
        }
    }
}

// ---------------------------------------------------------------------------
// Persistent LSTM recurrence: all 256 steps in ONE kernel.
// 128 CTAs x 256 threads, 1 CTA/SM (co-resident), grid barrier between steps.
// CTA owns 8 hidden units (32 gate rows). W_hh tile (32x1024 tf32 = 128 KB)
// is converted once and stays RESIDENT in smem. Per step, h (tf32) streams
// from L2 via cp.async.cg double-buffered chunks of BK=128.
// Warp layout: 8 warps = 2 m-tiles (m32) x 4 interleaved K-split groups.
// Warp tile m32 x n32; K-split partials reduced through gs in 4 phases.
// ---------------------------------------------------------------------------
#define W_STRIDE  1028
#define W_WORDS   (32 * W_STRIDE)            // 32896
#define PA_STRIDE 132
#define PA_BUF    (64 * PA_STRIDE)           // 8448
#define P_A_OFF   W_WORDS
#define P_GS_OFF  (P_A_OFF + 2 * PA_BUF)     // 49792
#define P_SMEM_WORDS (P_GS_OFF + 64 * 33)    // 51904
#define P_SMEM_BYTES (P_SMEM_WORDS * 4)      // 207616

__device__ __forceinline__ void grid_barrier(int target) {
    __syncthreads();
    if (threadIdx.x == 0) {
        __threadfence();
        unsigned old = atomicAdd(&g_bar_count, 1u);
        if (old == NCTA - 1) {
            g_bar_count = 0;
            __threadfence();
            g_bar_gen = (unsigned)target;
        } else {
            while (g_bar_gen < (unsigned)target) { }
        }
        __threadfence();
    }
    __syncthreads();
}

__global__ __launch_bounds__(256, 1)
void lstm_persistent(const float* __restrict__ W_hh,
                     float* __restrict__ outs, int out_size) {
    extern __shared__ unsigned smem[];
    unsigned* w_res = smem;
    unsigned* a_s   = smem + P_A_OFF;
    float*    gs    = (float*)(smem + P_GS_OFF);

    const int tid  = threadIdx.x;
    const int j0   = blockIdx.x * 8;
    const int w    = tid >> 5;
    const int lane = tid & 31;
    const int g    = lane >> 2;
    const int tig  = lane & 3;
    const int mt   = w & 1;          // m-tile: rows mt*32 .. +31
    const int kq   = w >> 1;         // K-split group 0..3
    const int m0   = mt * 32;

    // ---- Load W_hh tile resident in smem (fp32 -> tf32 once) ----
    {
        const int r    = tid >> 3;                 // local gate row 0..31
        const int cb   = (tid & 7) * 128;          // col base
        const int grow = (r >> 3) * D_HIDDEN + j0 + (r & 7);
        const float4* src = (const float4*)(W_hh + (size_t)grow * D_HIDDEN + cb);
        unsigned* dst = w_res + r * W_STRIDE + cb;
#pragma unroll
        for (int s = 0; s < 32; s++) {
            float4 v = src[s];
            dst[s * 4 + 0] = f2tf32(v.x);
            dst[s * 4 + 1] = f2tf32(v.y);
            dst[s * 4 + 2] = f2tf32(v.z);
            dst[s * 4 + 3] = f2tf32(v.w);
        }
    }
    __syncthreads();

    // Per-thread cell state: 2 adjacent cells (same batch, units cu, cu+1)
    const int cell0 = tid * 2;
    const int cb_b  = cell0 >> 3;    // batch 0..63
    const int cu    = cell0 & 7;     // unit (even)
    float c0 = 0.0f, c1 = 0.0f;

    // h-chunk loader indices
    const int arow = tid >> 2;             // 0..63
    const int ac0  = (tid & 3) * 32;       // 32 words per thread
    const unsigned sbase = (unsigned)__cvta_generic_to_shared(smem);
    const unsigned adst0 = sbase + (unsigned)(P_A_OFF + arow * PA_STRIDE + ac0) * 4;

    for (int t = 0; t < T_STEPS; t++) {
        // Prefetch this thread's x_gates early (sit in regs during MMA phase)
        const float* xgp = g_xgates + (size_t)t * BATCH * G4 + (size_t)cb_b * G4 + j0 + cu;
        const float2 xi = *(const float2*)(xgp);
        const float2 xf = *(const float2*)(xgp + D_HIDDEN);
        const float2 xg2 = *(const float2*)(xgp + 2 * D_HIDDEN);
        const float2 xo = *(const float2*)(xgp + 3 * D_HIDDEN);

        float cfr[2][4][4];
#pragma unroll
        for (int mi = 0; mi < 2; mi++)
#pragma unroll
            for (int na = 0; na < 4; na++)
#pragma unroll
                for (int q = 0; q < 4; q++) cfr[mi][na][q] = 0.0f;

        if (t > 0) {
            const unsigned* hrow = g_h_tf32[(t - 1) & 1] + (size_t)arow * D_HIDDEN + ac0;
#pragma unroll
            for (int s = 0; s < 8; s++) cpa16(adst0 + s * 16, hrow + s * 4);
            cpa_commit();

#pragma unroll 1
            for (int kc = 0; kc < 8; kc++) {
                const int buf = kc & 1;
                if (kc < 7) {
                    const unsigned* hn = hrow + (kc + 1) * 128;
                    const unsigned nd = adst0 + (unsigned)((buf ^ 1) * PA_BUF) * 4;
#pragma unroll
                    for (int s = 0; s < 8; s++) cpa16(nd + s * 16, hn + s * 4);
                    cpa_commit();
                    cpa_wait1();
                } else {
                    cpa_wait0();
                }
                __syncthreads();

                const unsigned* A  = a_s + buf * PA_BUF;
                const unsigned* Wc = w_res + kc * 128;
#pragma unroll
                for (int ki = 0; ki < 4; ki++) {
                    const int k8 = (ki * 4 + kq) * 8;   // interleaved K-split
                    unsigned af[2][4];
#pragma unroll
                    for (int mi = 0; mi < 2; mi++) {
                        const int rb = (m0 + mi * 16 + g) * PA_STRIDE;
                        af[mi][0] = A[rb + k8 + tig];
                        af[mi][1] = A[rb + 8 * PA_STRIDE + k8 + tig];
                        af[mi][2] = A[rb + k8 + tig + 4];
                        af[mi][3] = A[rb + 8 * PA_STRIDE + k8 + tig + 4];
                    }
#pragma unroll
                    for (int na = 0; na < 4; na++) {
                        const unsigned* wp = Wc + (na * 8 + g) * W_STRIDE + k8 + tig;
                        const unsigned b0 = wp[0];
                        const unsigned b1 = wp[4];
                        mma_tf32(cfr[0][na], af[0][0], af[0][1], af[0][2], af[0][3], b0, b1);
                        mma_tf32(cfr[1][na], af[1][0], af[1][1], af[1][2], af[1][3], b0, b1);
                    }
                }
                __syncthreads();
            }
        }

        // Reduce K-split partials into gs (4 phases)
#pragma unroll 1
        for (int ph = 0; ph < 4; ph++) {
            if (kq == ph) {
#pragma unroll
                for (int mi = 0; mi < 2; mi++) {
#pragma unroll
                    for (int na = 0; na < 4; na++) {
                        const int c = na * 8 + 2 * tig;
                        float* p0 = &gs[(m0 + mi * 16 + g) * 33 + c];
                        float* p1 = &gs[(m0 + mi * 16 + g + 8) * 33 + c];
                        if (ph == 0) {
                            p0[0] = cfr[mi][na][0]; p0[1] = cfr[mi][na][1];
                            p1[0] = cfr[mi][na][2]; p1[1] = cfr[mi][na][3];
                        } else {
                            p0[0] += cfr[mi][na][0]; p0[1] += cfr[mi][na][1];
                            p1[0] += cfr[mi][na][2]; p1[1] += cfr[mi][na][3];
                        }
                    }
                }
            }
            __syncthreads();
        }

        // Fused elementwise: 2 cells per thread
        const int gsrow = cb_b * 33;
        const float vi0 = gs[gsrow + cu]          + xi.x;
        const float vi1 = gs[gsrow + cu + 1]      + xi.y;
        const float vf0 = gs[gsrow + 8 + cu]      + xf.x;
        const float vf1 = gs[gsrow + 8 + cu + 1]  + xf.y;
        const float vg0 = gs[gsrow + 16 + cu]     + xg2.x;
        const float vg1 = gs[gsrow + 16 + cu + 1] + xg2.y;
        const float vo0 = gs[gsrow + 24 + cu]     + xo.x;
        const float vo1 = gs[gsrow + 24 + cu + 1] + xo.y;

        c0 = sigf(vf0) * c0 + sigf(vi0) * tanhf(vg0);
        c1 = sigf(vf1) * c1 + sigf(vi1) * tanhf(vg1);
        const float h0 = sigf(vo0) * tanhf(c0);
        const float h1 = sigf(vo1) * tanhf(c1);

        float* hp = outs + (size_t)t * NH + (size_t)cb_b * D_HIDDEN + j0 + cu;
        *(float2*)hp = make_float2(h0, h1);
        unsigned* tp = g_h_tf32[t & 1] + (size_t)cb_b * D_HIDDEN + j0 + cu;
        tp[0] = f2tf32(h0);
        tp[1] = f2tf32(h1);

        if (t == T_STEPS - 1) {
            const size_t base = (size_t)T_STEPS * NH;
            if ((size_t)out_size >= base + 2 * (size_t)NH) {
                float* tl = outs + base + (size_t)cb_b * D_HIDDEN + j0 + cu;
                *(float2*)tl = make_float2(h0, h1);
                *(float2*)(tl + NH) = make_float2(c0, c1);
            }
        } else {
            grid_barrier(t + 1);
        }
    }
}

// ---------------------------------------------------------------------------
extern "C" void kernel_launch(void* const* d_in, const int* in_sizes, int n_in,
                              void* d_out, int out_size)
{
    const int*   x_seq = (const int*)  d_in[0];
    const float* emb   = (const float*)d_in[1];
    const float* W_ih  = (const float*)d_in[2];
    const float* W_hh  = (const float*)d_in[3];
    const float* b_ih  = (const float*)d_in[4];
    const float* b_hh  = (const float*)d_in[5];
    float* out = (float*)d_out;

    cudaFuncSetAttribute(embed_gemm_tf32,
                         cudaFuncAttributeMaxDynamicSharedMemorySize, E_SMEM_BYTES);
    cudaFuncSetAttribute(lstm_persistent,
                         cudaFuncAttributeMaxDynamicSharedMemorySize, P_SMEM_BYTES);

    init_kernel<<<1, 1>>>();

    // Pre-convert embedding + W_ih to tf32 (W_hh converts inside persistent)
    {
        unsigned* demb; cudaGetSymbolAddress((void**)&demb, g_emb_tf32);
        unsigned* dwih; cudaGetSymbolAddress((void**)&dwih, g_wih_tf32);
        int n4e = (VOCAB * D_EMBED) / 4;
        int n4i = (G4 * D_EMBED) / 4;
        cvt_tf32_kernel<<<(n4e + 255) / 256, 256>>>((const float4*)emb,  (uint4*)demb, n4e);
        cvt_tf32_kernel<<<(n4i + 255) / 256, 256>>>((const float4*)W_ih, (uint4*)dwih, n4i);
    }

    dim3 eg(G4 / 128, (T_STEPS * BATCH) / 128);   // (32, 128)
    embed_gemm_tf32<<<eg, 256, E_SMEM_BYTES>>>(x_seq, b_ih, b_hh);

    lstm_persistent<<<NCTA, 256, P_SMEM_BYTES>>>(W_hh, out, out_size);
}

// round 6
// speedup vs baseline: 1.3489x; 1.2690x over previous
#include <cuda_runtime.h>
#include <math.h>
#include <stdint.h>

// Problem constants
#define T_STEPS  256
#define BATCH    64
#define VOCAB    32000
#define D_EMBED  512
#define D_HIDDEN 1024
#define G4       (4 * D_HIDDEN)          // 4096
#define NH       (BATCH * D_HIDDEN)      // 65536
#define NCTA     128

// Scratch
__device__ float    g_xgates[(size_t)T_STEPS * BATCH * G4];   // 256 MiB fp32
__device__ unsigned g_emb_tf32[(size_t)VOCAB * D_EMBED];      // tf32 bits
__device__ unsigned g_wih_tf32[(size_t)G4 * D_EMBED];
__device__ unsigned g_h_tf32[2][NH];                          // ping-pong h (tf32)
__device__ unsigned g_bar_count;
__device__ volatile unsigned g_bar_gen;

// ---------------------------------------------------------------------------
// Helpers
// ---------------------------------------------------------------------------
__device__ __forceinline__ unsigned f2tf32(float f) {
    unsigned u;
    asm("cvt.rna.tf32.f32 %0, %1;" : "=r"(u) : "f"(f));
    return u;
}

__device__ __forceinline__ void cpa16(unsigned dst_s, const void* src) {
    asm volatile("cp.async.cg.shared.global [%0], [%1], 16;" :: "r"(dst_s), "l"(src));
}
__device__ __forceinline__ void cpa_commit() {
    asm volatile("cp.async.commit_group;");
}
__device__ __forceinline__ void cpa_wait1() {
    asm volatile("cp.async.wait_group 1;");
}
__device__ __forceinline__ void cpa_wait0() {
    asm volatile("cp.async.wait_group 0;");
}

__device__ __forceinline__ void mma_tf32(float c[4],
                                         unsigned a0, unsigned a1, unsigned a2, unsigned a3,
                                         unsigned b0, unsigned b1) {
    asm volatile(
        "mma.sync.aligned.m16n8k8.row.col.f32.tf32.tf32.f32 "
        "{%0,%1,%2,%3}, {%4,%5,%6,%7}, {%8,%9}, {%0,%1,%2,%3};"
        : "+f"(c[0]), "+f"(c[1]), "+f"(c[2]), "+f"(c[3])
        : "r"(a0), "r"(a1), "r"(a2), "r"(a3), "r"(b0), "r"(b1));
}

// Fast sigmoid/tanh via MUFU (ex2 + approx div); abs err ~1e-6, safe vs 1e-3.
__device__ __forceinline__ float sigf(float x) {
    return __fdividef(1.0f, 1.0f + __expf(-x));
}
__device__ __forceinline__ float tanh_f(float x) {
    return 2.0f * __fdividef(1.0f, 1.0f + __expf(-2.0f * x)) - 1.0f;
}

// ---------------------------------------------------------------------------
// Init: reset grid-barrier state (fresh every launch for graph replay)
// ---------------------------------------------------------------------------
__global__ void init_kernel() {
    g_bar_count = 0;
    g_bar_gen = 0;
}

// ---------------------------------------------------------------------------
// fp32 -> tf32 (rna) bulk convert, vectorized x4
// ---------------------------------------------------------------------------
__global__ void cvt_tf32_kernel(const float4* __restrict__ src,
                                uint4* __restrict__ dst, int n4) {
    int i = blockIdx.x * blockDim.x + threadIdx.x;
    if (i < n4) {
        float4 v = src[i];
        uint4 o;
        o.x = f2tf32(v.x); o.y = f2tf32(v.y);
        o.z = f2tf32(v.z); o.w = f2tf32(v.w);
        dst[i] = o;
    }
}

// ---------------------------------------------------------------------------
// Embed gather + input GEMM (tf32 tensor cores)
//   x_gates[m][n] = sum_k emb[x_seq[m]][k] * W_ih[n][k] + b_ih[n] + b_hh[n]
// Now __launch_bounds__(256,2): 2 CTAs/SM for latency hiding (regs <= 128).
// ---------------------------------------------------------------------------
#define EA_STRIDE 36
#define EA_BUF    (128 * EA_STRIDE)
#define E_B_OFF   (2 * EA_BUF)
#define E_TOK_OFF (4 * EA_BUF)
#define E_SMEM_WORDS (E_TOK_OFF + 128)
#define E_SMEM_BYTES (E_SMEM_WORDS * 4)

__global__ __launch_bounds__(256, 2)
void embed_gemm_tf32(const int* __restrict__ x_seq,
                     const float* __restrict__ b_ih,
                     const float* __restrict__ b_hh) {
    extern __shared__ unsigned smem[];
    unsigned* a_s = smem;
    unsigned* b_s = smem + E_B_OFF;
    int*      tok = (int*)(smem + E_TOK_OFF);

    const int tid  = threadIdx.x;
    const int nblk = blockIdx.x * 128;
    const int mblk = blockIdx.y * 128;

    if (tid < 128) tok[tid] = x_seq[mblk + tid];
    __syncthreads();

    const int w    = tid >> 5;
    const int lane = tid & 31;
    const int g    = lane >> 2;
    const int tig  = lane & 3;
    const int m0   = (w & 3) * 32;
    const int n0   = (w >> 2) * 64;

    const int lrow = tid >> 1;
    const int lc0  = (tid & 1) * 16;

    const unsigned sbase = (unsigned)__cvta_generic_to_shared(smem);

    float cfr[2][8][4];
#pragma unroll
    for (int mi = 0; mi < 2; mi++)
#pragma unroll
        for (int ni = 0; ni < 8; ni++)
#pragma unroll
            for (int q = 0; q < 4; q++) cfr[mi][ni][q] = 0.0f;

    const unsigned* asrc_row = g_emb_tf32 + (size_t)tok[lrow] * D_EMBED + lc0;
    const unsigned* bsrc_row = g_wih_tf32 + (size_t)(nblk + lrow) * D_EMBED + lc0;

    auto load_chunk = [&](int kc, int buf) {
        unsigned adst = sbase + (buf * EA_BUF + lrow * EA_STRIDE + lc0) * 4;
        const unsigned* asrc = asrc_row + kc * 32;
#pragma unroll
        for (int s = 0; s < 4; s++) cpa16(adst + s * 16, asrc + s * 4);
        unsigned bdst = sbase + (E_B_OFF + buf * EA_BUF + lrow * EA_STRIDE + lc0) * 4;
        const unsigned* bsrc = bsrc_row + kc * 32;
#pragma unroll
        for (int s = 0; s < 4; s++) cpa16(bdst + s * 16, bsrc + s * 4);
    };

    load_chunk(0, 0);
    cpa_commit();

    for (int kc = 0; kc < 16; kc++) {
        const int buf = kc & 1;
        if (kc + 1 < 16) {
            load_chunk(kc + 1, buf ^ 1);
            cpa_commit();
            cpa_wait1();
        } else {
            cpa_wait0();
        }
        __syncthreads();

        const unsigned* A = a_s + buf * EA_BUF;
        const unsigned* B = b_s + buf * EA_BUF;
#pragma unroll
        for (int k8 = 0; k8 < 32; k8 += 8) {
            unsigned afr[2][4];
#pragma unroll
            for (int mi = 0; mi < 2; mi++) {
                const int r = m0 + mi * 16 + g;
                afr[mi][0] = A[r * EA_STRIDE + k8 + tig];
                afr[mi][1] = A[(r + 8) * EA_STRIDE + k8 + tig];
                afr[mi][2] = A[r * EA_STRIDE + k8 + tig + 4];
                afr[mi][3] = A[(r + 8) * EA_STRIDE + k8 + tig + 4];
            }
#pragma unroll
            for (int ni = 0; ni < 8; ni++) {
                const int r = n0 + ni * 8 + g;
                unsigned b0 = B[r * EA_STRIDE + k8 + tig];
                unsigned b1 = B[r * EA_STRIDE + k8 + tig + 4];
#pragma unroll
                for (int mi = 0; mi < 2; mi++)
                    mma_tf32(cfr[mi][ni], afr[mi][0], afr[mi][1], afr[mi][2], afr[mi][3], b0, b1);
            }
        }
        __syncthreads();
    }

#pragma unroll
    for (int ni = 0; ni < 8; ni++) {
        const int col = nblk + n0 + ni * 8 + 2 * tig;
        const float bi0 = b_ih[col] + b_hh[col];
        const float bi1 = b_ih[col + 1] + b_hh[col + 1];
#pragma unroll
        for (int mi = 0; mi < 2; mi++) {
            const int row = mblk + m0 + mi * 16 + g;
            float2 v0 = make_float2(cfr[mi][ni][0] + bi0, cfr[mi][ni][1] + bi1);
            float2 v1 = make_float2(cfr[mi][ni][2] + bi0, cfr[mi][ni][3] + bi1);
            *(float2*)&g_xgates[(size_t)row * G4 + col] = v0;
            *(float2*)&g_xgates[(size_t)(row + 8) * G4 + col] = v1;
        }
    }
}

// ---------------------------------------------------------------------------
// Persistent LSTM recurrence, 128 CTAs x 512 threads (16 warps).
// CTA owns 8 hidden units (32 gate rows), W tile (32x1024 tf32) resident in
// smem. Per step: h streams L2 -> smem via 3-buffer cp.async (BK=64, depth-2).
// Warp layout: 16 = 2(m: batch 32) x 2(n: gate-col 16) x 4(K-split).
// K-split partials go to 4 gs slices; single sync; fused elementwise.
// ---------------------------------------------------------------------------
#define PTHREADS  512
#define W_STRIDE  1028
#define W_WORDS   (32 * W_STRIDE)            // 32896
#define PA_STRIDE 68
#define PA_BUF    (64 * PA_STRIDE)           // 4352
#define P_A_OFF   W_WORDS
#define P_GS_OFF  (P_A_OFF + 3 * PA_BUF)     // 45952
#define GS_SLICE  (64 * 33)                  // 2112
#define P_SMEM_WORDS (P_GS_OFF + 4 * GS_SLICE)  // 54400
#define P_SMEM_BYTES (P_SMEM_WORDS * 4)         // 217600

__device__ __forceinline__ void grid_barrier(int target) {
    __syncthreads();
    if (threadIdx.x == 0) {
        __threadfence();
        unsigned old = atomicAdd(&g_bar_count, 1u);
        if (old == NCTA - 1) {
            g_bar_count = 0;
            __threadfence();
            g_bar_gen = (unsigned)target;
        } else {
            while (g_bar_gen < (unsigned)target) { }
        }
        __threadfence();
    }
    __syncthreads();
}

__global__ __launch_bounds__(PTHREADS, 1)
void lstm_persistent(const float* __restrict__ W_hh,
                     float* __restrict__ outs, int out_size) {
    extern __shared__ unsigned smem[];
    unsigned* w_res = smem;
    unsigned* a_s   = smem + P_A_OFF;
    float*    gs    = (float*)(smem + P_GS_OFF);

    const int tid  = threadIdx.x;
    const int j0   = blockIdx.x * 8;
    const int w    = tid >> 5;
    const int lane = tid & 31;
    const int g    = lane >> 2;
    const int tig  = lane & 3;
    const int m0   = (w & 1) * 32;          // batch tile base
    const int n0   = ((w >> 1) & 1) * 16;   // gate-col tile base
    const int ks   = w >> 2;                // K-split group 0..3

    // ---- W_hh tile resident (fp32 -> tf32 once) ----
    {
        const int r    = tid >> 4;                 // local gate row 0..31
        const int cb   = (tid & 15) * 64;          // col base
        const int grow = (r >> 3) * D_HIDDEN + j0 + (r & 7);
        const float4* src = (const float4*)(W_hh + (size_t)grow * D_HIDDEN + cb);
        unsigned* dst = w_res + r * W_STRIDE + cb;
#pragma unroll
        for (int s = 0; s < 16; s++) {
            float4 v = src[s];
            dst[s * 4 + 0] = f2tf32(v.x);
            dst[s * 4 + 1] = f2tf32(v.y);
            dst[s * 4 + 2] = f2tf32(v.z);
            dst[s * 4 + 3] = f2tf32(v.w);
        }
    }
    __syncthreads();

    // Cell mapping: 1 cell per thread
    const int cb_b = tid >> 3;     // batch 0..63
    const int cu   = tid & 7;      // unit 0..7
    float c_st = 0.0f;

    // h-chunk loader indices (chunk = 64 rows x 64 cols tf32 = 16 KB)
    const int arow = tid >> 3;             // 0..63
    const int acol = (tid & 7) * 8;        // 8 words per thread
    const unsigned sbase = (unsigned)__cvta_generic_to_shared(smem);
    const unsigned adst_base = sbase + (unsigned)(P_A_OFF + arow * PA_STRIDE + acol) * 4;

    // x_gates prefetch for t=0
    float xi, xf, xg2, xo;
    {
        const float* p = g_xgates + (size_t)cb_b * G4 + j0 + cu;
        xi  = p[0];
        xf  = p[D_HIDDEN];
        xg2 = p[2 * D_HIDDEN];
        xo  = p[3 * D_HIDDEN];
    }

    for (int t = 0; t < T_STEPS; t++) {
        float cfr[2][2][4];
#pragma unroll
        for (int mi = 0; mi < 2; mi++)
#pragma unroll
            for (int na = 0; na < 2; na++)
#pragma unroll
                for (int q = 0; q < 4; q++) cfr[mi][na][q] = 0.0f;

        if (t > 0) {
            const unsigned* hsrc = g_h_tf32[(t - 1) & 1] + (size_t)arow * D_HIDDEN + acol;
            // issue chunks 0, 1
            cpa16(adst_base, hsrc);
            cpa16(adst_base + 16, hsrc + 4);
            cpa_commit();
            {
                unsigned d1 = adst_base + (unsigned)PA_BUF * 4;
                cpa16(d1, hsrc + 64);
                cpa16(d1 + 16, hsrc + 68);
                cpa_commit();
            }

#pragma unroll 1
            for (int kc = 0; kc < 16; kc++) {
                if (kc < 15) cpa_wait1(); else cpa_wait0();
                __syncthreads();
                if (kc + 2 < 16) {
                    const int nbuf = (kc + 2) % 3;
                    unsigned d = adst_base + (unsigned)(nbuf * PA_BUF) * 4;
                    const unsigned* s = hsrc + (kc + 2) * 64;
                    cpa16(d, s);
                    cpa16(d + 16, s + 4);
                    cpa_commit();
                }

                const unsigned* A  = a_s + (kc % 3) * PA_BUF;
                const unsigned* Wc = w_res + kc * 64;
#pragma unroll
                for (int kk = 0; kk < 2; kk++) {
                    const int k8 = (kk * 4 + ks) * 8;
                    unsigned af[2][4];
#pragma unroll
                    for (int mi = 0; mi < 2; mi++) {
                        const int rb = (m0 + mi * 16 + g) * PA_STRIDE;
                        af[mi][0] = A[rb + k8 + tig];
                        af[mi][1] = A[rb + 8 * PA_STRIDE + k8 + tig];
                        af[mi][2] = A[rb + k8 + tig + 4];
                        af[mi][3] = A[rb + 8 * PA_STRIDE + k8 + tig + 4];
                    }
#pragma unroll
                    for (int na = 0; na < 2; na++) {
                        const unsigned* wp = Wc + (n0 + na * 8 + g) * W_STRIDE + k8 + tig;
                        const unsigned b0 = wp[0];
                        const unsigned b1 = wp[4];
                        mma_tf32(cfr[0][na], af[0][0], af[0][1], af[0][2], af[0][3], b0, b1);
                        mma_tf32(cfr[1][na], af[1][0], af[1][1], af[1][2], af[1][3], b0, b1);
                    }
                }
            }
        }

        // Write K-split partials to this group's gs slice (no phase serialization)
        {
            float* slice = gs + ks * GS_SLICE;
#pragma unroll
            for (int mi = 0; mi < 2; mi++) {
#pragma unroll
                for (int na = 0; na < 2; na++) {
                    const int c = n0 + na * 8 + 2 * tig;
                    float* p0 = slice + (m0 + mi * 16 + g) * 33 + c;
                    float* p1 = p0 + 8 * 33;
                    p0[0] = cfr[mi][na][0]; p0[1] = cfr[mi][na][1];
                    p1[0] = cfr[mi][na][2]; p1[1] = cfr[mi][na][3];
                }
            }
        }
        __syncthreads();

        // Fused elementwise: sum 4 slices + x_gates, activations, cell update
        float s0 = 0.0f, s1 = 0.0f, s2 = 0.0f, s3 = 0.0f;
#pragma unroll
        for (int q = 0; q < 4; q++) {
            const float* gp = gs + q * GS_SLICE + cb_b * 33 + cu;
            s0 += gp[0];
            s1 += gp[8];
            s2 += gp[16];
            s3 += gp[24];
        }
        const float vi = s0 + xi;
        const float vf = s1 + xf;
        const float vg = s2 + xg2;
        const float vo = s3 + xo;

        c_st = sigf(vf) * c_st + sigf(vi) * tanh_f(vg);
        const float hn = sigf(vo) * tanh_f(c_st);

        outs[(size_t)t * NH + (size_t)cb_b * D_HIDDEN + j0 + cu] = hn;
        g_h_tf32[t & 1][(size_t)cb_b * D_HIDDEN + j0 + cu] = f2tf32(hn);

        if (t == T_STEPS - 1) {
            const size_t base = (size_t)T_STEPS * NH;
            if ((size_t)out_size >= base + 2 * (size_t)NH) {
                const size_t off = (size_t)cb_b * D_HIDDEN + j0 + cu;
                outs[base + off]      = hn;
                outs[base + NH + off] = c_st;
            }
        } else {
            // prefetch x_gates for t+1 before the barrier (hides DRAM latency)
            const float* p = g_xgates + (size_t)(t + 1) * BATCH * G4
                           + (size_t)cb_b * G4 + j0 + cu;
            xi  = p[0];
            xf  = p[D_HIDDEN];
            xg2 = p[2 * D_HIDDEN];
            xo  = p[3 * D_HIDDEN];
            grid_barrier(t + 1);
        }
    }
}

// ---------------------------------------------------------------------------
extern "C" void kernel_launch(void* const* d_in, const int* in_sizes, int n_in,
                              void* d_out, int out_size)
{
    const int*   x_seq = (const int*)  d_in[0];
    const float* emb   = (const float*)d_in[1];
    const float* W_ih  = (const float*)d_in[2];
    const float* W_hh  = (const float*)d_in[3];
    const float* b_ih  = (const float*)d_in[4];
    const float* b_hh  = (const float*)d_in[5];
    float* out = (float*)d_out;

    cudaFuncSetAttribute(embed_gemm_tf32,
                         cudaFuncAttributeMaxDynamicSharedMemorySize, E_SMEM_BYTES);
    cudaFuncSetAttribute(lstm_persistent,
                         cudaFuncAttributeMaxDynamicSharedMemorySize, P_SMEM_BYTES);

    init_kernel<<<1, 1>>>();

    // Pre-convert embedding + W_ih to tf32 (W_hh converts inside persistent)
    {
        unsigned* demb; cudaGetSymbolAddress((void**)&demb, g_emb_tf32);
        unsigned* dwih; cudaGetSymbolAddress((void**)&dwih, g_wih_tf32);
        int n4e = (VOCAB * D_EMBED) / 4;
        int n4i = (G4 * D_EMBED) / 4;
        cvt_tf32_kernel<<<(n4e + 255) / 256, 256>>>((const float4*)emb,  (uint4*)demb, n4e);
        cvt_tf32_kernel<<<(n4i + 255) / 256, 256>>>((const float4*)W_ih, (uint4*)dwih, n4i);
    }

    dim3 eg(G4 / 128, (T_STEPS * BATCH) / 128);   // (32, 128)
    embed_gemm_tf32<<<eg, 256, E_SMEM_BYTES>>>(x_seq, b_ih, b_hh);

    lstm_persistent<<<NCTA, PTHREADS, P_SMEM_BYTES>>>(W_hh, out, out_size);
}